// round 12
// baseline (speedup 1.0000x reference)
#include <cuda_runtime.h>
#include <cuda_fp16.h>

#define Nn 100000
#define Ee 6400000
#define CF 1000
#define CAP 128
#define NTILES 3125           // Nn/32
#define FCBLOCKS 592

#define PDL_TRIGGER() asm volatile("griddepcontrol.launch_dependents;" ::: "memory")
#define PDL_WAIT()    asm volatile("griddepcontrol.wait;" ::: "memory")

// Static scratch (allocation-free rule). slot: 51.2 MB.
__device__ int    g_cnt[Nn];            // in-degree counter / bucket cursor
__device__ int    g_slot[Nn * CAP];     // neighbor (src) lists, bucketed by dst
__device__ float  g_dinv[Nn];
__device__ float2 g_xs[Nn];             // x * dinv  (layer-1 message)
__device__ uint4  g_h2h[Nn];            // layer-2 message: 8 x fp16 packed (16B)
__device__ unsigned long long g_z2[Nn * 8];  // z pre-packed {z,z} (u64)

__device__ __forceinline__ unsigned long long pack2(float lo, float hi) {
    unsigned long long r;
    asm("mov.b64 %0, {%1, %2};" : "=l"(r) : "f"(lo), "f"(hi));
    return r;
}
__device__ __forceinline__ unsigned long long fma2(unsigned long long a,
                                                   unsigned long long b,
                                                   unsigned long long c) {
    unsigned long long d;
    asm("fma.rn.f32x2 %0, %1, %2, %3;" : "=l"(d) : "l"(a), "l"(b), "l"(c));
    return d;
}
__device__ __forceinline__ float2 unpack2(unsigned long long v) {
    float lo, hi;
    asm("mov.b64 {%0, %1}, %2;" : "=f"(lo), "=f"(hi) : "l"(v));
    return make_float2(lo, hi);
}

__global__ void k_zero() {
    int i = blockIdx.x * blockDim.x + threadIdx.x;
    if (i < Nn) g_cnt[i] = 0;
}

// Build buckets: 4 edges/thread, atomics first, then dependent stores. (R8/R10)
__global__ void k_build(const int* __restrict__ ei) {
    int t = blockIdx.x * blockDim.x + threadIdx.x;
    if (t < Ee / 4) {
        int4 s4 = __ldg(&reinterpret_cast<const int4*>(ei)[t]);
        int4 d4 = __ldg(&reinterpret_cast<const int4*>(ei + Ee)[t]);
        int p0 = atomicAdd(&g_cnt[d4.x], 1);
        int p1 = atomicAdd(&g_cnt[d4.y], 1);
        int p2 = atomicAdd(&g_cnt[d4.z], 1);
        int p3 = atomicAdd(&g_cnt[d4.w], 1);
        if (p0 < CAP) g_slot[d4.x * CAP + p0] = s4.x;
        if (p1 < CAP) g_slot[d4.y * CAP + p1] = s4.y;
        if (p2 < CAP) g_slot[d4.z * CAP + p2] = s4.z;
        if (p3 < CAP) g_slot[d4.w * CAP + p3] = s4.w;
    }
}

__global__ void k_prep(const float* __restrict__ x) {
    int i = blockIdx.x * blockDim.x + threadIdx.x;
    if (i < Nn) {
        float d = rsqrtf((float)g_cnt[i] + 1.0f);   // +1 self loop
        g_dinv[i] = d;
        float2 xv = reinterpret_cast<const float2*>(x)[i];
        g_xs[i] = make_float2(xv.x * d, xv.y * d);
    }
    PDL_TRIGGER();
}

// Layer 1, warp-per-node: 32 lanes gather xs; deg/32 iterations, no intra-warp
// degree divergence. PDL on prep.
__global__ void __launch_bounds__(256) k_l1(const float* __restrict__ W1,
                                            const float* __restrict__ b1,
                                            const float* __restrict__ W2) {
    int node = (blockIdx.x * blockDim.x + threadIdx.x) >> 5;   // 1 warp = 1 node
    int lane = threadIdx.x & 31;

    // preamble: cnt/slot are build outputs (complete by chain transitivity)
    int deg = min(g_cnt[node], CAP);
    const int* sl = &g_slot[node * CAP];
    PDL_WAIT();   // xs/dinv (prep outputs) valid after this

    float a0 = 0.0f, a1 = 0.0f;
    int i = lane;
    for (; i + 32 < deg; i += 64) {
        int sA = __ldg(&sl[i]);
        int sB = __ldg(&sl[i + 32]);
        float2 vA = g_xs[sA];
        float2 vB = g_xs[sB];
        a0 += vA.x + vB.x;
        a1 += vA.y + vB.y;
    }
    if (i < deg) {
        int s = __ldg(&sl[i]);
        float2 v = g_xs[s];
        a0 += v.x;
        a1 += v.y;
    }
#pragma unroll
    for (int m = 1; m < 32; m <<= 1) {
        a0 += __shfl_xor_sync(0xFFFFFFFFu, a0, m);
        a1 += __shfl_xor_sync(0xFFFFFFFFu, a1, m);
    }
    float d = g_dinv[node];
    float2 self = g_xs[node];
    a0 = (a0 + self.x) * d;
    a1 = (a1 + self.y) * d;

    // lanes 0..7 compute output features 0..7 (others idle; tiny)
    if (lane < 8) {
        float acc = 0.0f;
#pragma unroll
        for (int j = 0; j < 16; j++) {
            float h = fmaf(a0, __ldg(&W1[j]), fmaf(a1, __ldg(&W1[16 + j]), __ldg(&b1[j])));
            h = fmaxf(h, 0.0f);
            acc = fmaf(h, __ldg(&W2[j * 8 + lane]), acc);
        }
        reinterpret_cast<__half*>(g_h2h)[node * 8 + lane] = __float2half_rn(acc * d);
    }
    PDL_TRIGGER();
}

__device__ __forceinline__ void acc8(float* a, uint4 v) {
    const __half2* hp = reinterpret_cast<const __half2*>(&v);
    float2 f0 = __half22float2(hp[0]);
    float2 f1 = __half22float2(hp[1]);
    float2 f2 = __half22float2(hp[2]);
    float2 f3 = __half22float2(hp[3]);
    a[0] += f0.x; a[1] += f0.y; a[2] += f1.x; a[3] += f1.y;
    a[4] += f2.x; a[5] += f2.y; a[6] += f3.x; a[7] += f3.y;
}

// Layer-2 aggregation, warp-per-node: 32 lanes gather h2h (16B each),
// 5-level butterfly on 8 accumulators, z pre-packed {z,z}. PDL on l1.
__global__ void __launch_bounds__(256) k_g2(const float* __restrict__ b2) {
    int node = (blockIdx.x * blockDim.x + threadIdx.x) >> 5;
    int lane = threadIdx.x & 31;

    int deg = min(g_cnt[node], CAP);          // build output: safe pre-wait
    const int* sl = &g_slot[node * CAP];
    float bias = (lane < 8) ? __ldg(&b2[lane]) : 0.0f;   // input: safe pre-wait
    PDL_WAIT();   // h2h (l1 output) valid after this

    float a[8] = {0, 0, 0, 0, 0, 0, 0, 0};
    int i = lane;
    for (; i + 32 < deg; i += 64) {
        int sA = __ldg(&sl[i]);
        int sB_ = __ldg(&sl[i + 32]);
        uint4 vA = g_h2h[sA];
        uint4 vB = g_h2h[sB_];
        acc8(a, vA);
        acc8(a, vB);
    }
    if (i < deg) acc8(a, g_h2h[__ldg(&sl[i])]);

#pragma unroll
    for (int m = 1; m < 32; m <<= 1) {
#pragma unroll
        for (int k = 0; k < 8; k++)
            a[k] += __shfl_xor_sync(0xFFFFFFFFu, a[k], m);
    }
    if (lane < 8) {
        float aj = a[0];
#pragma unroll
        for (int k = 1; k < 8; k++) if (lane == k) aj = a[k];
        float self = __half2float(reinterpret_cast<const __half*>(&g_h2h[node])[lane]);
        float zv = (aj + self) * g_dinv[node] + bias;
        g_z2[node * 8 + lane] = pack2(zv, zv);
    }
    PDL_TRIGGER();
}

// Persistent FC streamer (packed f32x2). Weight preamble before PDL wait.
__global__ void __launch_bounds__(256) k_out(const float* __restrict__ Wfc,
                                             const float* __restrict__ bfc,
                                             float* __restrict__ out) {
    __shared__ float sW[CF * 8];                 // Wfc transposed [c][k], 32 KB
    __shared__ unsigned long long sZ2[32][8];    // {z,z} packed, 2 KB

    int tid = threadIdx.x;

    for (int idx = tid; idx < CF * 8; idx += 256) {
        int k = idx / CF;
        int c = idx - k * CF;
        sW[c * 8 + k] = Wfc[idx];
    }
    __syncthreads();

    int c0 = tid * 4;
    bool active = (c0 < CF);
    unsigned long long wp01[8], wp23[8], bias01 = 0, bias23 = 0;
    if (active) {
#pragma unroll
        for (int k = 0; k < 8; k++) {
            wp01[k] = pack2(sW[(c0 + 0) * 8 + k], sW[(c0 + 1) * 8 + k]);
            wp23[k] = pack2(sW[(c0 + 2) * 8 + k], sW[(c0 + 3) * 8 + k]);
        }
        bias01 = pack2(__ldg(&bfc[c0 + 0]), __ldg(&bfc[c0 + 1]));
        bias23 = pack2(__ldg(&bfc[c0 + 2]), __ldg(&bfc[c0 + 3]));
    }

    PDL_WAIT();   // g_z2 (g2 output) valid after this

    for (int tile = blockIdx.x; tile < NTILES; tile += gridDim.x) {
        int node0 = tile * 32;
        __syncthreads();
        sZ2[tid >> 3][tid & 7] = g_z2[node0 * 8 + tid];
        __syncthreads();

        if (active) {
#pragma unroll 1
            for (int g = 0; g < 8; g++) {
#pragma unroll
                for (int n = 0; n < 4; n++) {
                    int nn = g * 4 + n;
                    unsigned long long acc01 = bias01, acc23 = bias23;
#pragma unroll
                    for (int k = 0; k < 8; k++) {
                        unsigned long long zb = sZ2[nn][k];
                        acc01 = fma2(zb, wp01[k], acc01);
                        acc23 = fma2(zb, wp23[k], acc23);
                    }
                    float2 r01 = unpack2(acc01);
                    float2 r23 = unpack2(acc23);
                    float4 r = make_float4(r01.x, r01.y, r23.x, r23.y);
                    int node = node0 + nn;
                    __stcs(reinterpret_cast<float4*>(&out[node * CF + c0]), r);
                }
            }
        }
    }
}

static inline void launch_pdl(void* func, dim3 grid, dim3 block, void** args) {
    cudaLaunchConfig_t cfg = {};
    cfg.gridDim = grid;
    cfg.blockDim = block;
    cfg.dynamicSmemBytes = 0;
    cfg.stream = 0;
    cudaLaunchAttribute attr[1];
    attr[0].id = cudaLaunchAttributeProgrammaticStreamSerialization;
    attr[0].val.programmaticStreamSerializationAllowed = 1;
    cfg.attrs = attr;
    cfg.numAttrs = 1;
    cudaLaunchKernelExC(&cfg, func, args);
}

extern "C" void kernel_launch(void* const* d_in, const int* in_sizes, int n_in,
                              void* d_out, int out_size) {
    const float* x   = (const float*)d_in[0];
    const int*   ei  = (const int*)d_in[1];
    const float* W1  = (const float*)d_in[2];
    const float* b1  = (const float*)d_in[3];
    const float* W2  = (const float*)d_in[4];
    const float* b2  = (const float*)d_in[5];
    const float* Wfc = (const float*)d_in[6];
    const float* bfc = (const float*)d_in[7];
    float* out = (float*)d_out;

    const int TB = 256;
    k_zero <<<(Nn + TB - 1) / TB, TB>>>();
    k_build<<<(Ee / 4 + TB - 1) / TB, TB>>>(ei);
    k_prep <<<(Nn + TB - 1) / TB, TB>>>(x);

    {   // k_l1 with PDL on k_prep  (warp-per-node: Nn/8 blocks of 256)
        void* args[] = {(void*)&W1, (void*)&b1, (void*)&W2};
        launch_pdl((void*)k_l1, dim3(Nn / 8), dim3(TB), args);
    }
    {   // k_g2 with PDL on k_l1
        void* args[] = {(void*)&b2};
        launch_pdl((void*)k_g2, dim3(Nn / 8), dim3(TB), args);
    }
    {   // k_out with PDL on k_g2
        void* args[] = {(void*)&Wfc, (void*)&bfc, (void*)&out};
        launch_pdl((void*)k_out, dim3(FCBLOCKS), dim3(TB), args);
    }
}

// round 13
// speedup vs baseline: 1.0945x; 1.0945x over previous
#include <cuda_runtime.h>
#include <cuda_fp16.h>

#define Nn 100000
#define Ee 6400000
#define CF 1000
#define CAP 128
#define NTILES 3125           // Nn/32
#define FCBLOCKS 592

#define PDL_TRIGGER() asm volatile("griddepcontrol.launch_dependents;" ::: "memory")
#define PDL_WAIT()    asm volatile("griddepcontrol.wait;" ::: "memory")

// Static scratch (allocation-free rule). slot: 51.2 MB.
__device__ int    g_cnt[Nn];            // in-degree counter / bucket cursor
__device__ int    g_slot[Nn * CAP];     // neighbor (src) lists, bucketed by dst
__device__ float  g_dinv[Nn];
__device__ float2 g_xs[Nn];             // x * dinv  (layer-1 message)
__device__ uint4  g_h2h[Nn];            // layer-2 message: 8 x fp16 packed (16B)
__device__ unsigned long long g_z2[Nn * 8];  // z pre-packed {z,z} (u64)

__device__ __forceinline__ unsigned long long pack2(float lo, float hi) {
    unsigned long long r;
    asm("mov.b64 %0, {%1, %2};" : "=l"(r) : "f"(lo), "f"(hi));
    return r;
}
__device__ __forceinline__ unsigned long long fma2(unsigned long long a,
                                                   unsigned long long b,
                                                   unsigned long long c) {
    unsigned long long d;
    asm("fma.rn.f32x2 %0, %1, %2, %3;" : "=l"(d) : "l"(a), "l"(b), "l"(c));
    return d;
}
__device__ __forceinline__ float2 unpack2(unsigned long long v) {
    float lo, hi;
    asm("mov.b64 {%0, %1}, %2;" : "=f"(lo), "=f"(hi) : "l"(v));
    return make_float2(lo, hi);
}

__global__ void k_zero() {
    int i = blockIdx.x * blockDim.x + threadIdx.x;
    if (i < Nn) g_cnt[i] = 0;
}

// Build buckets: 4 edges/thread, atomics first, then dependent stores.
__global__ void k_build(const int* __restrict__ ei) {
    int t = blockIdx.x * blockDim.x + threadIdx.x;
    if (t < Ee / 4) {
        int4 s4 = __ldg(&reinterpret_cast<const int4*>(ei)[t]);
        int4 d4 = __ldg(&reinterpret_cast<const int4*>(ei + Ee)[t]);
        int p0 = atomicAdd(&g_cnt[d4.x], 1);
        int p1 = atomicAdd(&g_cnt[d4.y], 1);
        int p2 = atomicAdd(&g_cnt[d4.z], 1);
        int p3 = atomicAdd(&g_cnt[d4.w], 1);
        if (p0 < CAP) g_slot[d4.x * CAP + p0] = s4.x;
        if (p1 < CAP) g_slot[d4.y * CAP + p1] = s4.y;
        if (p2 < CAP) g_slot[d4.z * CAP + p2] = s4.z;
        if (p3 < CAP) g_slot[d4.w * CAP + p3] = s4.w;
    }
}

__global__ void k_prep(const float* __restrict__ x) {
    int i = blockIdx.x * blockDim.x + threadIdx.x;
    if (i < Nn) {
        float d = rsqrtf((float)g_cnt[i] + 1.0f);   // +1 self loop
        g_dinv[i] = d;
        float2 xv = reinterpret_cast<const float2*>(x)[i];
        g_xs[i] = make_float2(xv.x * d, xv.y * d);
    }
    PDL_TRIGGER();
}

// Layer 1: 16 lanes/node gather xs, 2x unrolled; 4-level butterfly. PDL on prep.
__global__ void __launch_bounds__(256) k_l1(const float* __restrict__ W1,
                                            const float* __restrict__ b1,
                                            const float* __restrict__ W2) {
    int t = blockIdx.x * blockDim.x + threadIdx.x;
    int node = t >> 4;
    int lane = t & 15;

    // preamble: cnt/slot are build outputs (complete by chain transitivity)
    int deg = min(g_cnt[node], CAP);
    const int* sl = &g_slot[node * CAP];
    PDL_WAIT();   // xs/dinv (prep outputs) valid after this

    float a0 = 0.0f, a1 = 0.0f;
    int i = lane;
    for (; i + 16 < deg; i += 32) {
        int sA = __ldg(&sl[i]);
        int sB = __ldg(&sl[i + 16]);
        float2 vA = g_xs[sA];
        float2 vB = g_xs[sB];
        a0 += vA.x + vB.x;
        a1 += vA.y + vB.y;
    }
    if (i < deg) {
        int s = __ldg(&sl[i]);
        float2 v = g_xs[s];
        a0 += v.x;
        a1 += v.y;
    }
#pragma unroll
    for (int m = 1; m < 16; m <<= 1) {
        a0 += __shfl_xor_sync(0xFFFFFFFFu, a0, m);
        a1 += __shfl_xor_sync(0xFFFFFFFFu, a1, m);
    }
    float d = g_dinv[node];
    float2 self = g_xs[node];
    a0 = (a0 + self.x) * d;
    a1 = (a1 + self.y) * d;

    if (lane < 8) {   // lanes 0..7 of each 16-lane group: output feature = lane
        float acc = 0.0f;
#pragma unroll
        for (int j = 0; j < 16; j++) {
            float h = fmaf(a0, __ldg(&W1[j]), fmaf(a1, __ldg(&W1[16 + j]), __ldg(&b1[j])));
            h = fmaxf(h, 0.0f);
            acc = fmaf(h, __ldg(&W2[j * 8 + lane]), acc);
        }
        reinterpret_cast<__half*>(g_h2h)[node * 8 + lane] = __float2half_rn(acc * d);
    }
    PDL_TRIGGER();
}

__device__ __forceinline__ void acc8(float* a, uint4 v) {
    const __half2* hp = reinterpret_cast<const __half2*>(&v);
    float2 f0 = __half22float2(hp[0]);
    float2 f1 = __half22float2(hp[1]);
    float2 f2 = __half22float2(hp[2]);
    float2 f3 = __half22float2(hp[3]);
    a[0] += f0.x; a[1] += f0.y; a[2] += f1.x; a[3] += f1.y;
    a[4] += f2.x; a[5] += f2.y; a[6] += f3.x; a[7] += f3.y;
}

// Layer-2 aggregation: 16 lanes/node gather h2h (2x unrolled), 4-level
// butterfly over 8 accumulators, z pre-packed {z,z}. PDL on l1.
__global__ void __launch_bounds__(256) k_g2(const float* __restrict__ b2) {
    int t = blockIdx.x * blockDim.x + threadIdx.x;
    int node = t >> 4;
    int lane = t & 15;

    int deg = min(g_cnt[node], CAP);          // build output: safe pre-wait
    const int* sl = &g_slot[node * CAP];
    float bias = __ldg(&b2[lane & 7]);        // kernel input: safe pre-wait
    PDL_WAIT();   // h2h (l1 output) valid after this

    float a[8] = {0, 0, 0, 0, 0, 0, 0, 0};
    int i = lane;
    for (; i + 16 < deg; i += 32) {
        int sA = __ldg(&sl[i]);
        int sB_ = __ldg(&sl[i + 16]);
        uint4 vA = g_h2h[sA];
        uint4 vB = g_h2h[sB_];
        acc8(a, vA);
        acc8(a, vB);
    }
    if (i < deg) acc8(a, g_h2h[__ldg(&sl[i])]);

#pragma unroll
    for (int m = 1; m < 16; m <<= 1) {
#pragma unroll
        for (int k = 0; k < 8; k++)
            a[k] += __shfl_xor_sync(0xFFFFFFFFu, a[k], m);
    }
    if (lane < 8) {
        float aj = a[0];
#pragma unroll
        for (int k = 1; k < 8; k++) if (lane == k) aj = a[k];
        float self = __half2float(reinterpret_cast<const __half*>(&g_h2h[node])[lane]);
        float zv = (aj + self) * g_dinv[node] + bias;
        g_z2[node * 8 + lane] = pack2(zv, zv);
    }
    PDL_TRIGGER();
}

// Persistent FC streamer (packed f32x2). Weight preamble before PDL wait.
__global__ void __launch_bounds__(256) k_out(const float* __restrict__ Wfc,
                                             const float* __restrict__ bfc,
                                             float* __restrict__ out) {
    __shared__ float sW[CF * 8];                 // Wfc transposed [c][k], 32 KB
    __shared__ unsigned long long sZ2[32][8];    // {z,z} packed, 2 KB

    int tid = threadIdx.x;

    for (int idx = tid; idx < CF * 8; idx += 256) {
        int k = idx / CF;
        int c = idx - k * CF;
        sW[c * 8 + k] = Wfc[idx];
    }
    __syncthreads();

    int c0 = tid * 4;
    bool active = (c0 < CF);
    unsigned long long wp01[8], wp23[8], bias01 = 0, bias23 = 0;
    if (active) {
#pragma unroll
        for (int k = 0; k < 8; k++) {
            wp01[k] = pack2(sW[(c0 + 0) * 8 + k], sW[(c0 + 1) * 8 + k]);
            wp23[k] = pack2(sW[(c0 + 2) * 8 + k], sW[(c0 + 3) * 8 + k]);
        }
        bias01 = pack2(__ldg(&bfc[c0 + 0]), __ldg(&bfc[c0 + 1]));
        bias23 = pack2(__ldg(&bfc[c0 + 2]), __ldg(&bfc[c0 + 3]));
    }

    PDL_WAIT();   // g_z2 (g2 output) valid after this

    for (int tile = blockIdx.x; tile < NTILES; tile += gridDim.x) {
        int node0 = tile * 32;
        __syncthreads();
        sZ2[tid >> 3][tid & 7] = g_z2[node0 * 8 + tid];
        __syncthreads();

        if (active) {
#pragma unroll 1
            for (int g = 0; g < 8; g++) {
#pragma unroll
                for (int n = 0; n < 4; n++) {
                    int nn = g * 4 + n;
                    unsigned long long acc01 = bias01, acc23 = bias23;
#pragma unroll
                    for (int k = 0; k < 8; k++) {
                        unsigned long long zb = sZ2[nn][k];
                        acc01 = fma2(zb, wp01[k], acc01);
                        acc23 = fma2(zb, wp23[k], acc23);
                    }
                    float2 r01 = unpack2(acc01);
                    float2 r23 = unpack2(acc23);
                    float4 r = make_float4(r01.x, r01.y, r23.x, r23.y);
                    int node = node0 + nn;
                    __stcs(reinterpret_cast<float4*>(&out[node * CF + c0]), r);
                }
            }
        }
    }
}

static inline void launch_pdl(void* func, dim3 grid, dim3 block, void** args) {
    cudaLaunchConfig_t cfg = {};
    cfg.gridDim = grid;
    cfg.blockDim = block;
    cfg.dynamicSmemBytes = 0;
    cfg.stream = 0;
    cudaLaunchAttribute attr[1];
    attr[0].id = cudaLaunchAttributeProgrammaticStreamSerialization;
    attr[0].val.programmaticStreamSerializationAllowed = 1;
    cfg.attrs = attr;
    cfg.numAttrs = 1;
    cudaLaunchKernelExC(&cfg, func, args);
}

extern "C" void kernel_launch(void* const* d_in, const int* in_sizes, int n_in,
                              void* d_out, int out_size) {
    const float* x   = (const float*)d_in[0];
    const int*   ei  = (const int*)d_in[1];
    const float* W1  = (const float*)d_in[2];
    const float* b1  = (const float*)d_in[3];
    const float* W2  = (const float*)d_in[4];
    const float* b2  = (const float*)d_in[5];
    const float* Wfc = (const float*)d_in[6];
    const float* bfc = (const float*)d_in[7];
    float* out = (float*)d_out;

    const int TB = 256;
    k_zero <<<(Nn + TB - 1) / TB, TB>>>();
    k_build<<<(Ee / 4 + TB - 1) / TB, TB>>>(ei);
    k_prep <<<(Nn + TB - 1) / TB, TB>>>(x);

    {   // k_l1 with PDL on k_prep  (16 lanes/node: Nn/16 blocks of 256)
        void* args[] = {(void*)&W1, (void*)&b1, (void*)&W2};
        launch_pdl((void*)k_l1, dim3(Nn / 16), dim3(TB), args);
    }
    {   // k_g2 with PDL on k_l1
        void* args[] = {(void*)&b2};
        launch_pdl((void*)k_g2, dim3(Nn / 16), dim3(TB), args);
    }
    {   // k_out with PDL on k_g2
        void* args[] = {(void*)&Wfc, (void*)&bfc, (void*)&out};
        launch_pdl((void*)k_out, dim3(FCBLOCKS), dim3(TB), args);
    }
}

// round 14
// speedup vs baseline: 1.1209x; 1.0242x over previous
#include <cuda_runtime.h>
#include <cuda_fp16.h>

#define Nn 100000
#define Ee 6400000
#define CF 1000
#define CAP 128
#define NTILES 3125           // Nn/32
#define FCBLOCKS 592

#define PDL_TRIGGER() asm volatile("griddepcontrol.launch_dependents;" ::: "memory")
#define PDL_WAIT()    asm volatile("griddepcontrol.wait;" ::: "memory")

// Static scratch (allocation-free rule). slot: 51.2 MB.
__device__ int    g_cnt[Nn];            // in-degree counter / bucket cursor
__device__ int    g_slot[Nn * CAP];     // neighbor (src) lists, bucketed by dst
__device__ float  g_dinv[Nn];
__device__ float2 g_xs[Nn];             // x * dinv  (layer-1 message)
__device__ uint4  g_h2h[Nn];            // layer-2 message: 8 x fp16 packed (16B)
__device__ unsigned long long g_z2[Nn * 8];  // z pre-packed {z,z} (u64)

__device__ __forceinline__ unsigned long long pack2(float lo, float hi) {
    unsigned long long r;
    asm("mov.b64 %0, {%1, %2};" : "=l"(r) : "f"(lo), "f"(hi));
    return r;
}
__device__ __forceinline__ unsigned long long fma2(unsigned long long a,
                                                   unsigned long long b,
                                                   unsigned long long c) {
    unsigned long long d;
    asm("fma.rn.f32x2 %0, %1, %2, %3;" : "=l"(d) : "l"(a), "l"(b), "l"(c));
    return d;
}
__device__ __forceinline__ float2 unpack2(unsigned long long v) {
    float lo, hi;
    asm("mov.b64 {%0, %1}, %2;" : "=f"(lo), "=f"(hi) : "l"(v));
    return make_float2(lo, hi);
}

__global__ void k_zero() {
    int i = blockIdx.x * blockDim.x + threadIdx.x;
    if (i < Nn) g_cnt[i] = 0;
}

// Build buckets: 4 edges/thread, atomics first, then dependent stores.
__global__ void k_build(const int* __restrict__ ei) {
    int t = blockIdx.x * blockDim.x + threadIdx.x;
    if (t < Ee / 4) {
        int4 s4 = __ldg(&reinterpret_cast<const int4*>(ei)[t]);
        int4 d4 = __ldg(&reinterpret_cast<const int4*>(ei + Ee)[t]);
        int p0 = atomicAdd(&g_cnt[d4.x], 1);
        int p1 = atomicAdd(&g_cnt[d4.y], 1);
        int p2 = atomicAdd(&g_cnt[d4.z], 1);
        int p3 = atomicAdd(&g_cnt[d4.w], 1);
        if (p0 < CAP) g_slot[d4.x * CAP + p0] = s4.x;
        if (p1 < CAP) g_slot[d4.y * CAP + p1] = s4.y;
        if (p2 < CAP) g_slot[d4.z * CAP + p2] = s4.z;
        if (p3 < CAP) g_slot[d4.w * CAP + p3] = s4.w;
    }
}

__global__ void k_prep(const float* __restrict__ x) {
    int i = blockIdx.x * blockDim.x + threadIdx.x;
    if (i < Nn) {
        float d = rsqrtf((float)g_cnt[i] + 1.0f);   // +1 self loop
        g_dinv[i] = d;
        float2 xv = reinterpret_cast<const float2*>(x)[i];
        g_xs[i] = make_float2(xv.x * d, xv.y * d);
    }
    PDL_TRIGGER();
}

// Layer 1: gather xs over neighbors (8 lanes/node), 2x unrolled. PDL on prep.
__global__ void __launch_bounds__(256) k_l1(const float* __restrict__ W1,
                                            const float* __restrict__ b1,
                                            const float* __restrict__ W2) {
    int t = blockIdx.x * blockDim.x + threadIdx.x;
    int node = t >> 3;
    int lane = t & 7;
    if (node >= Nn) { PDL_WAIT(); PDL_TRIGGER(); return; }

    // preamble: cnt/slot are build outputs (guaranteed complete by chain order)
    int deg = min(g_cnt[node], CAP);
    const int* sl = &g_slot[node * CAP];
    PDL_WAIT();   // xs/dinv (prep outputs) valid after this

    float a0 = 0.0f, a1 = 0.0f;
    int i = lane;
    for (; i + 8 < deg; i += 16) {
        int sA = __ldg(&sl[i]);
        int sB = __ldg(&sl[i + 8]);
        float2 vA = g_xs[sA];
        float2 vB = g_xs[sB];
        a0 += vA.x + vB.x;
        a1 += vA.y + vB.y;
    }
    if (i < deg) {
        int s = __ldg(&sl[i]);
        float2 v = g_xs[s];
        a0 += v.x;
        a1 += v.y;
    }
#pragma unroll
    for (int m = 1; m < 8; m <<= 1) {
        a0 += __shfl_xor_sync(0xFFFFFFFFu, a0, m);
        a1 += __shfl_xor_sync(0xFFFFFFFFu, a1, m);
    }
    float d = g_dinv[node];
    float2 self = g_xs[node];
    a0 = (a0 + self.x) * d;
    a1 = (a1 + self.y) * d;

    float h1[16];
#pragma unroll
    for (int j = 0; j < 16; j++) {
        float v = fmaf(a0, __ldg(&W1[j]), fmaf(a1, __ldg(&W1[16 + j]), __ldg(&b1[j])));
        h1[j] = fmaxf(v, 0.0f);
    }
    float acc = 0.0f;
#pragma unroll
    for (int j = 0; j < 16; j++) acc = fmaf(h1[j], __ldg(&W2[j * 8 + lane]), acc);
    reinterpret_cast<__half*>(g_h2h)[node * 8 + lane] = __float2half_rn(acc * d);
    PDL_TRIGGER();
}

__device__ __forceinline__ void acc8(float* a, uint4 v) {
    const __half2* hp = reinterpret_cast<const __half2*>(&v);
    float2 f0 = __half22float2(hp[0]);
    float2 f1 = __half22float2(hp[1]);
    float2 f2 = __half22float2(hp[2]);
    float2 f3 = __half22float2(hp[3]);
    a[0] += f0.x; a[1] += f0.y; a[2] += f1.x; a[3] += f1.y;
    a[4] += f2.x; a[5] += f2.y; a[6] += f3.x; a[7] += f3.y;
}

// Layer-2 aggregation: 8 lanes/node gather h2h (2x unrolled),
// z = (agg + self) * dinv + b2, stored pre-packed {z,z}. PDL on l1.
__global__ void __launch_bounds__(256) k_g2(const float* __restrict__ b2) {
    int t = blockIdx.x * blockDim.x + threadIdx.x;
    int node = t >> 3;
    int lane = t & 7;
    if (node >= Nn) { PDL_WAIT(); PDL_TRIGGER(); return; }

    int deg = min(g_cnt[node], CAP);          // build output: safe pre-wait
    const int* sl = &g_slot[node * CAP];
    float bias = __ldg(&b2[lane]);            // kernel input: safe pre-wait
    PDL_WAIT();   // h2h (l1 output) valid after this

    float a[8] = {0, 0, 0, 0, 0, 0, 0, 0};
    int i = lane;
    for (; i + 8 < deg; i += 16) {
        int sA = __ldg(&sl[i]);
        int sB_ = __ldg(&sl[i + 8]);
        uint4 vA = g_h2h[sA];
        uint4 vB = g_h2h[sB_];
        acc8(a, vA);
        acc8(a, vB);
    }
    if (i < deg) acc8(a, g_h2h[__ldg(&sl[i])]);

#pragma unroll
    for (int m = 1; m < 8; m <<= 1) {
#pragma unroll
        for (int k = 0; k < 8; k++)
            a[k] += __shfl_xor_sync(0xFFFFFFFFu, a[k], m);
    }
    float aj = a[0];
#pragma unroll
    for (int k = 1; k < 8; k++) if (lane == k) aj = a[k];
    float self = __half2float(reinterpret_cast<const __half*>(&g_h2h[node])[lane]);
    float zv = (aj + self) * g_dinv[node] + bias;
    g_z2[node * 8 + lane] = pack2(zv, zv);
    PDL_TRIGGER();
}

// Persistent FC streamer (packed f32x2). Weight preamble runs BEFORE the PDL
// wait, overlapping k_g2's tail. Per node: 8 LDS.64 + 16 fma.f32x2 + STG.128.
__global__ void __launch_bounds__(256) k_out(const float* __restrict__ Wfc,
                                             const float* __restrict__ bfc,
                                             float* __restrict__ out) {
    __shared__ float sW[CF * 8];                 // Wfc transposed [c][k], 32 KB
    __shared__ unsigned long long sZ2[32][8];    // {z,z} packed, 2 KB

    int tid = threadIdx.x;

    // ---- preamble: weights only (kernel inputs), safe before PDL wait ----
    for (int idx = tid; idx < CF * 8; idx += 256) {
        int k = idx / CF;
        int c = idx - k * CF;
        sW[c * 8 + k] = Wfc[idx];
    }
    __syncthreads();

    int c0 = tid * 4;
    bool active = (c0 < CF);
    unsigned long long wp01[8], wp23[8], bias01 = 0, bias23 = 0;
    if (active) {
#pragma unroll
        for (int k = 0; k < 8; k++) {
            wp01[k] = pack2(sW[(c0 + 0) * 8 + k], sW[(c0 + 1) * 8 + k]);
            wp23[k] = pack2(sW[(c0 + 2) * 8 + k], sW[(c0 + 3) * 8 + k]);
        }
        bias01 = pack2(__ldg(&bfc[c0 + 0]), __ldg(&bfc[c0 + 1]));
        bias23 = pack2(__ldg(&bfc[c0 + 2]), __ldg(&bfc[c0 + 3]));
    }

    PDL_WAIT();   // g_z2 (g2 output) valid after this

    for (int tile = blockIdx.x; tile < NTILES; tile += gridDim.x) {
        int node0 = tile * 32;
        __syncthreads();
        sZ2[tid >> 3][tid & 7] = g_z2[node0 * 8 + tid];
        __syncthreads();

        if (active) {
#pragma unroll 1
            for (int g = 0; g < 8; g++) {
#pragma unroll
                for (int n = 0; n < 4; n++) {
                    int nn = g * 4 + n;
                    unsigned long long acc01 = bias01, acc23 = bias23;
#pragma unroll
                    for (int k = 0; k < 8; k++) {
                        unsigned long long zb = sZ2[nn][k];
                        acc01 = fma2(zb, wp01[k], acc01);
                        acc23 = fma2(zb, wp23[k], acc23);
                    }
                    float2 r01 = unpack2(acc01);
                    float2 r23 = unpack2(acc23);
                    float4 r = make_float4(r01.x, r01.y, r23.x, r23.y);
                    int node = node0 + nn;
                    __stcs(reinterpret_cast<float4*>(&out[node * CF + c0]), r);
                }
            }
        }
    }
}

static inline void launch_pdl(void* func, dim3 grid, dim3 block,
                              void** args) {
    cudaLaunchConfig_t cfg = {};
    cfg.gridDim = grid;
    cfg.blockDim = block;
    cfg.dynamicSmemBytes = 0;
    cfg.stream = 0;
    cudaLaunchAttribute attr[1];
    attr[0].id = cudaLaunchAttributeProgrammaticStreamSerialization;
    attr[0].val.programmaticStreamSerializationAllowed = 1;
    cfg.attrs = attr;
    cfg.numAttrs = 1;
    cudaLaunchKernelExC(&cfg, func, args);
}

extern "C" void kernel_launch(void* const* d_in, const int* in_sizes, int n_in,
                              void* d_out, int out_size) {
    const float* x   = (const float*)d_in[0];
    const int*   ei  = (const int*)d_in[1];
    const float* W1  = (const float*)d_in[2];
    const float* b1  = (const float*)d_in[3];
    const float* W2  = (const float*)d_in[4];
    const float* b2  = (const float*)d_in[5];
    const float* Wfc = (const float*)d_in[6];
    const float* bfc = (const float*)d_in[7];
    float* out = (float*)d_out;

    const int TB = 256;
    k_zero <<<(Nn + TB - 1) / TB, TB>>>();
    k_build<<<(Ee / 4 + TB - 1) / TB, TB>>>(ei);
    k_prep <<<(Nn + TB - 1) / TB, TB>>>(x);

    {   // k_l1 with PDL on k_prep
        void* args[] = {(void*)&W1, (void*)&b1, (void*)&W2};
        launch_pdl((void*)k_l1, dim3((Nn * 8 + TB - 1) / TB), dim3(TB), args);
    }
    {   // k_g2 with PDL on k_l1
        void* args[] = {(void*)&b2};
        launch_pdl((void*)k_g2, dim3((Nn * 8 + TB - 1) / TB), dim3(TB), args);
    }
    {   // k_out with PDL on k_g2
        void* args[] = {(void*)&Wfc, (void*)&bfc, (void*)&out};
        launch_pdl((void*)k_out, dim3(FCBLOCKS), dim3(TB), args);
    }
}

// round 15
// speedup vs baseline: 1.1344x; 1.0120x over previous
#include <cuda_runtime.h>
#include <cuda_fp16.h>

#define Nn 100000
#define Ee 6400000
#define CF 1000
#define CAP 128
#define NTILES 3125           // Nn/32
#define FCBLOCKS 592

#define PDL_TRIGGER() asm volatile("griddepcontrol.launch_dependents;" ::: "memory")
#define PDL_WAIT()    asm volatile("griddepcontrol.wait;" ::: "memory")

// Static scratch (allocation-free rule). slot: 51.2 MB.
__device__ int    g_cnt[Nn];            // in-degree counter / bucket cursor
__device__ int    g_slot[Nn * CAP];     // neighbor (src) lists, bucketed by dst
__device__ float  g_dinv[Nn];
__device__ float2 g_xs[Nn];             // x * dinv  (layer-1 message)
__device__ uint4  g_h2h[Nn];            // layer-2 message: 8 x fp16 packed (16B)
__device__ unsigned long long g_z2[Nn * 8];  // z pre-packed {z,z} (u64)

__device__ __forceinline__ unsigned long long pack2(float lo, float hi) {
    unsigned long long r;
    asm("mov.b64 %0, {%1, %2};" : "=l"(r) : "f"(lo), "f"(hi));
    return r;
}
__device__ __forceinline__ unsigned long long fma2(unsigned long long a,
                                                   unsigned long long b,
                                                   unsigned long long c) {
    unsigned long long d;
    asm("fma.rn.f32x2 %0, %1, %2, %3;" : "=l"(d) : "l"(a), "l"(b), "l"(c));
    return d;
}
__device__ __forceinline__ float2 unpack2(unsigned long long v) {
    float lo, hi;
    asm("mov.b64 {%0, %1}, %2;" : "=f"(lo), "=f"(hi) : "l"(v));
    return make_float2(lo, hi);
}

__global__ void k_zero() {
    int i = blockIdx.x * blockDim.x + threadIdx.x;
    if (i < Nn) g_cnt[i] = 0;
    PDL_TRIGGER();
}

// Build buckets: 4 edges/thread, atomics first, then dependent stores.
// Edge-index reads are evict-first (streamed once) to preserve L2 for the
// slot array. PDL: waits on k_zero only after its input loads are in flight.
__global__ void k_build(const int* __restrict__ ei) {
    int t = blockIdx.x * blockDim.x + threadIdx.x;
    if (t < Ee / 4) {
        int4 s4 = __ldcs(&reinterpret_cast<const int4*>(ei)[t]);
        int4 d4 = __ldcs(&reinterpret_cast<const int4*>(ei + Ee)[t]);
        PDL_WAIT();   // g_cnt zeroed
        int p0 = atomicAdd(&g_cnt[d4.x], 1);
        int p1 = atomicAdd(&g_cnt[d4.y], 1);
        int p2 = atomicAdd(&g_cnt[d4.z], 1);
        int p3 = atomicAdd(&g_cnt[d4.w], 1);
        if (p0 < CAP) g_slot[d4.x * CAP + p0] = s4.x;
        if (p1 < CAP) g_slot[d4.y * CAP + p1] = s4.y;
        if (p2 < CAP) g_slot[d4.z * CAP + p2] = s4.z;
        if (p3 < CAP) g_slot[d4.w * CAP + p3] = s4.w;
    } else {
        PDL_WAIT();
    }
    PDL_TRIGGER();
}

__global__ void k_prep(const float* __restrict__ x) {
    int i = blockIdx.x * blockDim.x + threadIdx.x;
    if (i < Nn) {
        float2 xv = reinterpret_cast<const float2*>(x)[i];   // input: safe pre-wait
        PDL_WAIT();   // g_cnt final
        float d = rsqrtf((float)g_cnt[i] + 1.0f);   // +1 self loop
        g_dinv[i] = d;
        g_xs[i] = make_float2(xv.x * d, xv.y * d);
    } else {
        PDL_WAIT();
    }
    PDL_TRIGGER();
}

// Layer 1: gather xs over neighbors (8 lanes/node), 2x unrolled. PDL on prep.
__global__ void __launch_bounds__(256) k_l1(const float* __restrict__ W1,
                                            const float* __restrict__ b1,
                                            const float* __restrict__ W2) {
    int t = blockIdx.x * blockDim.x + threadIdx.x;
    int node = t >> 3;
    int lane = t & 7;
    if (node >= Nn) { PDL_WAIT(); PDL_TRIGGER(); return; }

    // preamble: cnt/slot are build outputs (guaranteed complete by chain order)
    int deg = min(g_cnt[node], CAP);
    const int* sl = &g_slot[node * CAP];
    PDL_WAIT();   // xs/dinv (prep outputs) valid after this

    float a0 = 0.0f, a1 = 0.0f;
    int i = lane;
    for (; i + 8 < deg; i += 16) {
        int sA = __ldg(&sl[i]);
        int sB = __ldg(&sl[i + 8]);
        float2 vA = g_xs[sA];
        float2 vB = g_xs[sB];
        a0 += vA.x + vB.x;
        a1 += vA.y + vB.y;
    }
    if (i < deg) {
        int s = __ldg(&sl[i]);
        float2 v = g_xs[s];
        a0 += v.x;
        a1 += v.y;
    }
#pragma unroll
    for (int m = 1; m < 8; m <<= 1) {
        a0 += __shfl_xor_sync(0xFFFFFFFFu, a0, m);
        a1 += __shfl_xor_sync(0xFFFFFFFFu, a1, m);
    }
    float d = g_dinv[node];
    float2 self = g_xs[node];
    a0 = (a0 + self.x) * d;
    a1 = (a1 + self.y) * d;

    float h1[16];
#pragma unroll
    for (int j = 0; j < 16; j++) {
        float v = fmaf(a0, __ldg(&W1[j]), fmaf(a1, __ldg(&W1[16 + j]), __ldg(&b1[j])));
        h1[j] = fmaxf(v, 0.0f);
    }
    float acc = 0.0f;
#pragma unroll
    for (int j = 0; j < 16; j++) acc = fmaf(h1[j], __ldg(&W2[j * 8 + lane]), acc);
    reinterpret_cast<__half*>(g_h2h)[node * 8 + lane] = __float2half_rn(acc * d);
    PDL_TRIGGER();
}

__device__ __forceinline__ void acc8(float* a, uint4 v) {
    const __half2* hp = reinterpret_cast<const __half2*>(&v);
    float2 f0 = __half22float2(hp[0]);
    float2 f1 = __half22float2(hp[1]);
    float2 f2 = __half22float2(hp[2]);
    float2 f3 = __half22float2(hp[3]);
    a[0] += f0.x; a[1] += f0.y; a[2] += f1.x; a[3] += f1.y;
    a[4] += f2.x; a[5] += f2.y; a[6] += f3.x; a[7] += f3.y;
}

// Layer-2 aggregation: 8 lanes/node gather h2h (2x unrolled),
// z = (agg + self) * dinv + b2, stored pre-packed {z,z}. PDL on l1.
__global__ void __launch_bounds__(256) k_g2(const float* __restrict__ b2) {
    int t = blockIdx.x * blockDim.x + threadIdx.x;
    int node = t >> 3;
    int lane = t & 7;
    if (node >= Nn) { PDL_WAIT(); PDL_TRIGGER(); return; }

    int deg = min(g_cnt[node], CAP);          // build output: safe pre-wait
    const int* sl = &g_slot[node * CAP];
    float bias = __ldg(&b2[lane]);            // kernel input: safe pre-wait
    PDL_WAIT();   // h2h (l1 output) valid after this

    float a[8] = {0, 0, 0, 0, 0, 0, 0, 0};
    int i = lane;
    for (; i + 8 < deg; i += 16) {
        int sA = __ldg(&sl[i]);
        int sB_ = __ldg(&sl[i + 8]);
        uint4 vA = g_h2h[sA];
        uint4 vB = g_h2h[sB_];
        acc8(a, vA);
        acc8(a, vB);
    }
    if (i < deg) acc8(a, g_h2h[__ldg(&sl[i])]);

#pragma unroll
    for (int m = 1; m < 8; m <<= 1) {
#pragma unroll
        for (int k = 0; k < 8; k++)
            a[k] += __shfl_xor_sync(0xFFFFFFFFu, a[k], m);
    }
    float aj = a[0];
#pragma unroll
    for (int k = 1; k < 8; k++) if (lane == k) aj = a[k];
    float self = __half2float(reinterpret_cast<const __half*>(&g_h2h[node])[lane]);
    float zv = (aj + self) * g_dinv[node] + bias;
    g_z2[node * 8 + lane] = pack2(zv, zv);
    PDL_TRIGGER();
}

// Persistent FC streamer (packed f32x2). Weight preamble runs BEFORE the PDL
// wait, overlapping k_g2's tail. Per node: 8 LDS.64 + 16 fma.f32x2 + STG.128.
__global__ void __launch_bounds__(256) k_out(const float* __restrict__ Wfc,
                                             const float* __restrict__ bfc,
                                             float* __restrict__ out) {
    __shared__ float sW[CF * 8];                 // Wfc transposed [c][k], 32 KB
    __shared__ unsigned long long sZ2[32][8];    // {z,z} packed, 2 KB

    int tid = threadIdx.x;

    // ---- preamble: weights only (kernel inputs), safe before PDL wait ----
    for (int idx = tid; idx < CF * 8; idx += 256) {
        int k = idx / CF;
        int c = idx - k * CF;
        sW[c * 8 + k] = Wfc[idx];
    }
    __syncthreads();

    int c0 = tid * 4;
    bool active = (c0 < CF);
    unsigned long long wp01[8], wp23[8], bias01 = 0, bias23 = 0;
    if (active) {
#pragma unroll
        for (int k = 0; k < 8; k++) {
            wp01[k] = pack2(sW[(c0 + 0) * 8 + k], sW[(c0 + 1) * 8 + k]);
            wp23[k] = pack2(sW[(c0 + 2) * 8 + k], sW[(c0 + 3) * 8 + k]);
        }
        bias01 = pack2(__ldg(&bfc[c0 + 0]), __ldg(&bfc[c0 + 1]));
        bias23 = pack2(__ldg(&bfc[c0 + 2]), __ldg(&bfc[c0 + 3]));
    }

    PDL_WAIT();   // g_z2 (g2 output) valid after this

    for (int tile = blockIdx.x; tile < NTILES; tile += gridDim.x) {
        int node0 = tile * 32;
        __syncthreads();
        sZ2[tid >> 3][tid & 7] = g_z2[node0 * 8 + tid];
        __syncthreads();

        if (active) {
#pragma unroll 1
            for (int g = 0; g < 8; g++) {
#pragma unroll
                for (int n = 0; n < 4; n++) {
                    int nn = g * 4 + n;
                    unsigned long long acc01 = bias01, acc23 = bias23;
#pragma unroll
                    for (int k = 0; k < 8; k++) {
                        unsigned long long zb = sZ2[nn][k];
                        acc01 = fma2(zb, wp01[k], acc01);
                        acc23 = fma2(zb, wp23[k], acc23);
                    }
                    float2 r01 = unpack2(acc01);
                    float2 r23 = unpack2(acc23);
                    float4 r = make_float4(r01.x, r01.y, r23.x, r23.y);
                    int node = node0 + nn;
                    __stcs(reinterpret_cast<float4*>(&out[node * CF + c0]), r);
                }
            }
        }
    }
}

static inline void launch_pdl(void* func, dim3 grid, dim3 block,
                              void** args) {
    cudaLaunchConfig_t cfg = {};
    cfg.gridDim = grid;
    cfg.blockDim = block;
    cfg.dynamicSmemBytes = 0;
    cfg.stream = 0;
    cudaLaunchAttribute attr[1];
    attr[0].id = cudaLaunchAttributeProgrammaticStreamSerialization;
    attr[0].val.programmaticStreamSerializationAllowed = 1;
    cfg.attrs = attr;
    cfg.numAttrs = 1;
    cudaLaunchKernelExC(&cfg, func, args);
}

extern "C" void kernel_launch(void* const* d_in, const int* in_sizes, int n_in,
                              void* d_out, int out_size) {
    const float* x   = (const float*)d_in[0];
    const int*   ei  = (const int*)d_in[1];
    const float* W1  = (const float*)d_in[2];
    const float* b1  = (const float*)d_in[3];
    const float* W2  = (const float*)d_in[4];
    const float* b2  = (const float*)d_in[5];
    const float* Wfc = (const float*)d_in[6];
    const float* bfc = (const float*)d_in[7];
    float* out = (float*)d_out;

    const int TB = 256;
    k_zero<<<(Nn + TB - 1) / TB, TB>>>();

    {   // k_build with PDL on k_zero
        void* args[] = {(void*)&ei};
        launch_pdl((void*)k_build, dim3((Ee / 4 + TB - 1) / TB), dim3(TB), args);
    }
    {   // k_prep with PDL on k_build
        void* args[] = {(void*)&x};
        launch_pdl((void*)k_prep, dim3((Nn + TB - 1) / TB), dim3(TB), args);
    }
    {   // k_l1 with PDL on k_prep
        void* args[] = {(void*)&W1, (void*)&b1, (void*)&W2};
        launch_pdl((void*)k_l1, dim3((Nn * 8 + TB - 1) / TB), dim3(TB), args);
    }
    {   // k_g2 with PDL on k_l1
        void* args[] = {(void*)&b2};
        launch_pdl((void*)k_g2, dim3((Nn * 8 + TB - 1) / TB), dim3(TB), args);
    }
    {   // k_out with PDL on k_g2
        void* args[] = {(void*)&Wfc, (void*)&bfc, (void*)&out};
        launch_pdl((void*)k_out, dim3(FCBLOCKS), dim3(TB), args);
    }
}

// round 16
// speedup vs baseline: 1.1411x; 1.0059x over previous
#include <cuda_runtime.h>
#include <cuda_fp16.h>

#define Nn 100000
#define Ee 6400000
#define CF 1000
#define CAP 128
#define NTILES 3125           // Nn/32
#define FCBLOCKS 740

#define PDL_TRIGGER() asm volatile("griddepcontrol.launch_dependents;" ::: "memory")
#define PDL_WAIT()    asm volatile("griddepcontrol.wait;" ::: "memory")

// Static scratch (allocation-free rule). slot: 51.2 MB.
__device__ int    g_cnt[Nn];            // in-degree counter / bucket cursor
__device__ int    g_slot[Nn * CAP];     // neighbor (src) lists, bucketed by dst
__device__ float  g_dinv[Nn];
__device__ float2 g_xs[Nn];             // x * dinv  (layer-1 message)
__device__ uint4  g_h2h[Nn];            // layer-2 message: 8 x fp16 packed (16B)
__device__ unsigned long long g_z2[Nn * 8];  // z pre-packed {z,z} (u64)

__device__ __forceinline__ unsigned long long pack2(float lo, float hi) {
    unsigned long long r;
    asm("mov.b64 %0, {%1, %2};" : "=l"(r) : "f"(lo), "f"(hi));
    return r;
}
__device__ __forceinline__ unsigned long long fma2(unsigned long long a,
                                                   unsigned long long b,
                                                   unsigned long long c) {
    unsigned long long d;
    asm("fma.rn.f32x2 %0, %1, %2, %3;" : "=l"(d) : "l"(a), "l"(b), "l"(c));
    return d;
}
__device__ __forceinline__ float2 unpack2(unsigned long long v) {
    float lo, hi;
    asm("mov.b64 {%0, %1}, %2;" : "=f"(lo), "=f"(hi) : "l"(v));
    return make_float2(lo, hi);
}

__global__ void k_zero() {
    int i = blockIdx.x * blockDim.x + threadIdx.x;
    if (i < Nn) g_cnt[i] = 0;
    PDL_TRIGGER();
}

// Build buckets: 4 edges/thread, atomics first, then dependent stores.
// Edge-index reads are evict-first (streamed once) to preserve L2 for the
// slot array. PDL: waits on k_zero only after its input loads are in flight.
__global__ void k_build(const int* __restrict__ ei) {
    int t = blockIdx.x * blockDim.x + threadIdx.x;
    if (t < Ee / 4) {
        int4 s4 = __ldcs(&reinterpret_cast<const int4*>(ei)[t]);
        int4 d4 = __ldcs(&reinterpret_cast<const int4*>(ei + Ee)[t]);
        PDL_WAIT();   // g_cnt zeroed
        int p0 = atomicAdd(&g_cnt[d4.x], 1);
        int p1 = atomicAdd(&g_cnt[d4.y], 1);
        int p2 = atomicAdd(&g_cnt[d4.z], 1);
        int p3 = atomicAdd(&g_cnt[d4.w], 1);
        if (p0 < CAP) g_slot[d4.x * CAP + p0] = s4.x;
        if (p1 < CAP) g_slot[d4.y * CAP + p1] = s4.y;
        if (p2 < CAP) g_slot[d4.z * CAP + p2] = s4.z;
        if (p3 < CAP) g_slot[d4.w * CAP + p3] = s4.w;
    } else {
        PDL_WAIT();
    }
    PDL_TRIGGER();
}

__global__ void k_prep(const float* __restrict__ x) {
    int i = blockIdx.x * blockDim.x + threadIdx.x;
    if (i < Nn) {
        float2 xv = __ldcs(&reinterpret_cast<const float2*>(x)[i]);  // read-once stream
        PDL_WAIT();   // g_cnt final
        float d = rsqrtf((float)g_cnt[i] + 1.0f);   // +1 self loop
        g_dinv[i] = d;
        g_xs[i] = make_float2(xv.x * d, xv.y * d);
    } else {
        PDL_WAIT();
    }
    PDL_TRIGGER();
}

// Layer 1: gather xs over neighbors (8 lanes/node), 2x unrolled. PDL on prep.
__global__ void __launch_bounds__(256) k_l1(const float* __restrict__ W1,
                                            const float* __restrict__ b1,
                                            const float* __restrict__ W2) {
    int t = blockIdx.x * blockDim.x + threadIdx.x;
    int node = t >> 3;
    int lane = t & 7;
    if (node >= Nn) { PDL_WAIT(); PDL_TRIGGER(); return; }

    // preamble: cnt/slot are build outputs (guaranteed complete by chain order)
    int deg = min(g_cnt[node], CAP);
    const int* sl = &g_slot[node * CAP];
    PDL_WAIT();   // xs/dinv (prep outputs) valid after this

    float a0 = 0.0f, a1 = 0.0f;
    int i = lane;
    for (; i + 8 < deg; i += 16) {
        int sA = __ldg(&sl[i]);
        int sB = __ldg(&sl[i + 8]);
        float2 vA = g_xs[sA];
        float2 vB = g_xs[sB];
        a0 += vA.x + vB.x;
        a1 += vA.y + vB.y;
    }
    if (i < deg) {
        int s = __ldg(&sl[i]);
        float2 v = g_xs[s];
        a0 += v.x;
        a1 += v.y;
    }
#pragma unroll
    for (int m = 1; m < 8; m <<= 1) {
        a0 += __shfl_xor_sync(0xFFFFFFFFu, a0, m);
        a1 += __shfl_xor_sync(0xFFFFFFFFu, a1, m);
    }
    float d = g_dinv[node];
    float2 self = g_xs[node];
    a0 = (a0 + self.x) * d;
    a1 = (a1 + self.y) * d;

    float h1[16];
#pragma unroll
    for (int j = 0; j < 16; j++) {
        float v = fmaf(a0, __ldg(&W1[j]), fmaf(a1, __ldg(&W1[16 + j]), __ldg(&b1[j])));
        h1[j] = fmaxf(v, 0.0f);
    }
    float acc = 0.0f;
#pragma unroll
    for (int j = 0; j < 16; j++) acc = fmaf(h1[j], __ldg(&W2[j * 8 + lane]), acc);
    reinterpret_cast<__half*>(g_h2h)[node * 8 + lane] = __float2half_rn(acc * d);
    PDL_TRIGGER();
}

__device__ __forceinline__ void acc8(float* a, uint4 v) {
    const __half2* hp = reinterpret_cast<const __half2*>(&v);
    float2 f0 = __half22float2(hp[0]);
    float2 f1 = __half22float2(hp[1]);
    float2 f2 = __half22float2(hp[2]);
    float2 f3 = __half22float2(hp[3]);
    a[0] += f0.x; a[1] += f0.y; a[2] += f1.x; a[3] += f1.y;
    a[4] += f2.x; a[5] += f2.y; a[6] += f3.x; a[7] += f3.y;
}

// Layer-2 aggregation: 8 lanes/node gather h2h (2x unrolled),
// z = (agg + self) * dinv + b2, stored pre-packed {z,z}. PDL on l1.
__global__ void __launch_bounds__(256) k_g2(const float* __restrict__ b2) {
    int t = blockIdx.x * blockDim.x + threadIdx.x;
    int node = t >> 3;
    int lane = t & 7;
    if (node >= Nn) { PDL_WAIT(); PDL_TRIGGER(); return; }

    int deg = min(g_cnt[node], CAP);          // build output: safe pre-wait
    const int* sl = &g_slot[node * CAP];
    float bias = __ldg(&b2[lane]);            // kernel input: safe pre-wait
    PDL_WAIT();   // h2h (l1 output) valid after this

    float a[8] = {0, 0, 0, 0, 0, 0, 0, 0};
    int i = lane;
    for (; i + 8 < deg; i += 16) {
        int sA = __ldg(&sl[i]);
        int sB_ = __ldg(&sl[i + 8]);
        uint4 vA = g_h2h[sA];
        uint4 vB = g_h2h[sB_];
        acc8(a, vA);
        acc8(a, vB);
    }
    if (i < deg) acc8(a, g_h2h[__ldg(&sl[i])]);

#pragma unroll
    for (int m = 1; m < 8; m <<= 1) {
#pragma unroll
        for (int k = 0; k < 8; k++)
            a[k] += __shfl_xor_sync(0xFFFFFFFFu, a[k], m);
    }
    float aj = a[0];
#pragma unroll
    for (int k = 1; k < 8; k++) if (lane == k) aj = a[k];
    float self = __half2float(reinterpret_cast<const __half*>(&g_h2h[node])[lane]);
    float zv = (aj + self) * g_dinv[node] + bias;
    g_z2[node * 8 + lane] = pack2(zv, zv);
    PDL_TRIGGER();
}

// Persistent FC streamer (packed f32x2). Weight preamble runs BEFORE the PDL
// wait, overlapping k_g2's tail. Per node: 8 LDS.64 + 16 fma.f32x2 + STG.128.
__global__ void __launch_bounds__(256) k_out(const float* __restrict__ Wfc,
                                             const float* __restrict__ bfc,
                                             float* __restrict__ out) {
    __shared__ float sW[CF * 8];                 // Wfc transposed [c][k], 32 KB
    __shared__ unsigned long long sZ2[32][8];    // {z,z} packed, 2 KB

    int tid = threadIdx.x;

    // ---- preamble: weights only (kernel inputs), safe before PDL wait ----
    for (int idx = tid; idx < CF * 8; idx += 256) {
        int k = idx / CF;
        int c = idx - k * CF;
        sW[c * 8 + k] = Wfc[idx];
    }
    __syncthreads();

    int c0 = tid * 4;
    bool active = (c0 < CF);
    unsigned long long wp01[8], wp23[8], bias01 = 0, bias23 = 0;
    if (active) {
#pragma unroll
        for (int k = 0; k < 8; k++) {
            wp01[k] = pack2(sW[(c0 + 0) * 8 + k], sW[(c0 + 1) * 8 + k]);
            wp23[k] = pack2(sW[(c0 + 2) * 8 + k], sW[(c0 + 3) * 8 + k]);
        }
        bias01 = pack2(__ldg(&bfc[c0 + 0]), __ldg(&bfc[c0 + 1]));
        bias23 = pack2(__ldg(&bfc[c0 + 2]), __ldg(&bfc[c0 + 3]));
    }

    PDL_WAIT();   // g_z2 (g2 output) valid after this

    for (int tile = blockIdx.x; tile < NTILES; tile += gridDim.x) {
        int node0 = tile * 32;
        __syncthreads();
        sZ2[tid >> 3][tid & 7] = g_z2[node0 * 8 + tid];
        __syncthreads();

        if (active) {
#pragma unroll 1
            for (int g = 0; g < 8; g++) {
#pragma unroll
                for (int n = 0; n < 4; n++) {
                    int nn = g * 4 + n;
                    unsigned long long acc01 = bias01, acc23 = bias23;
#pragma unroll
                    for (int k = 0; k < 8; k++) {
                        unsigned long long zb = sZ2[nn][k];
                        acc01 = fma2(zb, wp01[k], acc01);
                        acc23 = fma2(zb, wp23[k], acc23);
                    }
                    float2 r01 = unpack2(acc01);
                    float2 r23 = unpack2(acc23);
                    float4 r = make_float4(r01.x, r01.y, r23.x, r23.y);
                    int node = node0 + nn;
                    __stcs(reinterpret_cast<float4*>(&out[node * CF + c0]), r);
                }
            }
        }
    }
}

static inline void launch_pdl(void* func, dim3 grid, dim3 block,
                              void** args) {
    cudaLaunchConfig_t cfg = {};
    cfg.gridDim = grid;
    cfg.blockDim = block;
    cfg.dynamicSmemBytes = 0;
    cfg.stream = 0;
    cudaLaunchAttribute attr[1];
    attr[0].id = cudaLaunchAttributeProgrammaticStreamSerialization;
    attr[0].val.programmaticStreamSerializationAllowed = 1;
    cfg.attrs = attr;
    cfg.numAttrs = 1;
    cudaLaunchKernelExC(&cfg, func, args);
}

extern "C" void kernel_launch(void* const* d_in, const int* in_sizes, int n_in,
                              void* d_out, int out_size) {
    const float* x   = (const float*)d_in[0];
    const int*   ei  = (const int*)d_in[1];
    const float* W1  = (const float*)d_in[2];
    const float* b1  = (const float*)d_in[3];
    const float* W2  = (const float*)d_in[4];
    const float* b2  = (const float*)d_in[5];
    const float* Wfc = (const float*)d_in[6];
    const float* bfc = (const float*)d_in[7];
    float* out = (float*)d_out;

    const int TB = 256;
    k_zero<<<(Nn + TB - 1) / TB, TB>>>();

    {   // k_build with PDL on k_zero
        void* args[] = {(void*)&ei};
        launch_pdl((void*)k_build, dim3((Ee / 4 + TB - 1) / TB), dim3(TB), args);
    }
    {   // k_prep with PDL on k_build
        void* args[] = {(void*)&x};
        launch_pdl((void*)k_prep, dim3((Nn + TB - 1) / TB), dim3(TB), args);
    }
    {   // k_l1 with PDL on k_prep
        void* args[] = {(void*)&W1, (void*)&b1, (void*)&W2};
        launch_pdl((void*)k_l1, dim3((Nn * 8 + TB - 1) / TB), dim3(TB), args);
    }
    {   // k_g2 with PDL on k_l1
        void* args[] = {(void*)&b2};
        launch_pdl((void*)k_g2, dim3((Nn * 8 + TB - 1) / TB), dim3(TB), args);
    }
    {   // k_out with PDL on k_g2
        void* args[] = {(void*)&Wfc, (void*)&bfc, (void*)&out};
        launch_pdl((void*)k_out, dim3(FCBLOCKS), dim3(TB), args);
    }
}

// round 17
// speedup vs baseline: 1.1598x; 1.0164x over previous
#include <cuda_runtime.h>
#include <cuda_fp16.h>

#define Nn 100000
#define Ee 6400000
#define CF 1000
#define CAP 128
#define NTILES 3125           // Nn/32
#define FCBLOCKS 740

#define PDL_TRIGGER() asm volatile("griddepcontrol.launch_dependents;" ::: "memory")
#define PDL_WAIT()    asm volatile("griddepcontrol.wait;" ::: "memory")

// Static scratch (allocation-free rule). slot: 51.2 MB.
// g_cnt starts zero-initialized (module load) and is RE-ZEROED by k_out at the
// end of every call, so each call/replay begins from a clean state.
__device__ int    g_cnt[Nn];            // in-degree counter / bucket cursor
__device__ int    g_slot[Nn * CAP];     // neighbor (src) lists, bucketed by dst
__device__ float  g_dinv[Nn];
__device__ float2 g_xs[Nn];             // x * dinv  (layer-1 message)
__device__ uint4  g_h2h[Nn];            // layer-2 message: 8 x fp16 packed (16B)
__device__ unsigned long long g_z2[Nn * 8];  // z pre-packed {z,z} (u64)

__device__ __forceinline__ unsigned long long pack2(float lo, float hi) {
    unsigned long long r;
    asm("mov.b64 %0, {%1, %2};" : "=l"(r) : "f"(lo), "f"(hi));
    return r;
}
__device__ __forceinline__ unsigned long long fma2(unsigned long long a,
                                                   unsigned long long b,
                                                   unsigned long long c) {
    unsigned long long d;
    asm("fma.rn.f32x2 %0, %1, %2, %3;" : "=l"(d) : "l"(a), "l"(b), "l"(c));
    return d;
}
__device__ __forceinline__ float2 unpack2(unsigned long long v) {
    float lo, hi;
    asm("mov.b64 {%0, %1}, %2;" : "=f"(lo), "=f"(hi) : "l"(v));
    return make_float2(lo, hi);
}

// Build buckets: 4 edges/thread, atomics first, then dependent stores.
// Edge-index reads are evict-first (streamed once) to preserve L2 for the
// slot array. Launched PLAINLY (no PDL): stream order guarantees the previous
// call's k_out has finished re-zeroing g_cnt.
__global__ void k_build(const int* __restrict__ ei) {
    int t = blockIdx.x * blockDim.x + threadIdx.x;
    if (t < Ee / 4) {
        int4 s4 = __ldcs(&reinterpret_cast<const int4*>(ei)[t]);
        int4 d4 = __ldcs(&reinterpret_cast<const int4*>(ei + Ee)[t]);
        int p0 = atomicAdd(&g_cnt[d4.x], 1);
        int p1 = atomicAdd(&g_cnt[d4.y], 1);
        int p2 = atomicAdd(&g_cnt[d4.z], 1);
        int p3 = atomicAdd(&g_cnt[d4.w], 1);
        if (p0 < CAP) g_slot[d4.x * CAP + p0] = s4.x;
        if (p1 < CAP) g_slot[d4.y * CAP + p1] = s4.y;
        if (p2 < CAP) g_slot[d4.z * CAP + p2] = s4.z;
        if (p3 < CAP) g_slot[d4.w * CAP + p3] = s4.w;
    }
    PDL_TRIGGER();
}

__global__ void k_prep(const float* __restrict__ x) {
    int i = blockIdx.x * blockDim.x + threadIdx.x;
    if (i < Nn) {
        float2 xv = __ldcs(&reinterpret_cast<const float2*>(x)[i]);  // read-once stream
        PDL_WAIT();   // g_cnt final
        float d = rsqrtf((float)g_cnt[i] + 1.0f);   // +1 self loop
        g_dinv[i] = d;
        g_xs[i] = make_float2(xv.x * d, xv.y * d);
    } else {
        PDL_WAIT();
    }
    PDL_TRIGGER();
}

// Layer 1: gather xs over neighbors (8 lanes/node), 2x unrolled. PDL on prep.
__global__ void __launch_bounds__(256) k_l1(const float* __restrict__ W1,
                                            const float* __restrict__ b1,
                                            const float* __restrict__ W2) {
    int t = blockIdx.x * blockDim.x + threadIdx.x;
    int node = t >> 3;
    int lane = t & 7;
    if (node >= Nn) { PDL_WAIT(); PDL_TRIGGER(); return; }

    // preamble: cnt/slot are build outputs (guaranteed complete by chain order)
    int deg = min(g_cnt[node], CAP);
    const int* sl = &g_slot[node * CAP];
    PDL_WAIT();   // xs/dinv (prep outputs) valid after this

    float a0 = 0.0f, a1 = 0.0f;
    int i = lane;
    for (; i + 8 < deg; i += 16) {
        int sA = __ldg(&sl[i]);
        int sB = __ldg(&sl[i + 8]);
        float2 vA = g_xs[sA];
        float2 vB = g_xs[sB];
        a0 += vA.x + vB.x;
        a1 += vA.y + vB.y;
    }
    if (i < deg) {
        int s = __ldg(&sl[i]);
        float2 v = g_xs[s];
        a0 += v.x;
        a1 += v.y;
    }
#pragma unroll
    for (int m = 1; m < 8; m <<= 1) {
        a0 += __shfl_xor_sync(0xFFFFFFFFu, a0, m);
        a1 += __shfl_xor_sync(0xFFFFFFFFu, a1, m);
    }
    float d = g_dinv[node];
    float2 self = g_xs[node];
    a0 = (a0 + self.x) * d;
    a1 = (a1 + self.y) * d;

    float h1[16];
#pragma unroll
    for (int j = 0; j < 16; j++) {
        float v = fmaf(a0, __ldg(&W1[j]), fmaf(a1, __ldg(&W1[16 + j]), __ldg(&b1[j])));
        h1[j] = fmaxf(v, 0.0f);
    }
    float acc = 0.0f;
#pragma unroll
    for (int j = 0; j < 16; j++) acc = fmaf(h1[j], __ldg(&W2[j * 8 + lane]), acc);
    reinterpret_cast<__half*>(g_h2h)[node * 8 + lane] = __float2half_rn(acc * d);
    PDL_TRIGGER();
}

__device__ __forceinline__ void acc8(float* a, uint4 v) {
    const __half2* hp = reinterpret_cast<const __half2*>(&v);
    float2 f0 = __half22float2(hp[0]);
    float2 f1 = __half22float2(hp[1]);
    float2 f2 = __half22float2(hp[2]);
    float2 f3 = __half22float2(hp[3]);
    a[0] += f0.x; a[1] += f0.y; a[2] += f1.x; a[3] += f1.y;
    a[4] += f2.x; a[5] += f2.y; a[6] += f3.x; a[7] += f3.y;
}

// Layer-2 aggregation: 8 lanes/node gather h2h (2x unrolled),
// z = (agg + self) * dinv + b2, stored pre-packed {z,z}. PDL on l1.
__global__ void __launch_bounds__(256) k_g2(const float* __restrict__ b2) {
    int t = blockIdx.x * blockDim.x + threadIdx.x;
    int node = t >> 3;
    int lane = t & 7;
    if (node >= Nn) { PDL_WAIT(); PDL_TRIGGER(); return; }

    int deg = min(g_cnt[node], CAP);          // build output: safe pre-wait
    const int* sl = &g_slot[node * CAP];
    float bias = __ldg(&b2[lane]);            // kernel input: safe pre-wait
    PDL_WAIT();   // h2h (l1 output) valid after this

    float a[8] = {0, 0, 0, 0, 0, 0, 0, 0};
    int i = lane;
    for (; i + 8 < deg; i += 16) {
        int sA = __ldg(&sl[i]);
        int sB_ = __ldg(&sl[i + 8]);
        uint4 vA = g_h2h[sA];
        uint4 vB = g_h2h[sB_];
        acc8(a, vA);
        acc8(a, vB);
    }
    if (i < deg) acc8(a, g_h2h[__ldg(&sl[i])]);

#pragma unroll
    for (int m = 1; m < 8; m <<= 1) {
#pragma unroll
        for (int k = 0; k < 8; k++)
            a[k] += __shfl_xor_sync(0xFFFFFFFFu, a[k], m);
    }
    float aj = a[0];
#pragma unroll
    for (int k = 1; k < 8; k++) if (lane == k) aj = a[k];
    float self = __half2float(reinterpret_cast<const __half*>(&g_h2h[node])[lane]);
    float zv = (aj + self) * g_dinv[node] + bias;
    g_z2[node * 8 + lane] = pack2(zv, zv);
    PDL_TRIGGER();
}

// Persistent FC streamer (packed f32x2). Weight preamble runs BEFORE the PDL
// wait, overlapping k_g2's tail. Per node: 8 LDS.64 + 16 fma.f32x2 + STG.128.
// EPILOGUE: re-zeros g_cnt so the next call/replay starts clean (replaces the
// k_zero kernel).
__global__ void __launch_bounds__(256) k_out(const float* __restrict__ Wfc,
                                             const float* __restrict__ bfc,
                                             float* __restrict__ out) {
    __shared__ float sW[CF * 8];                 // Wfc transposed [c][k], 32 KB
    __shared__ unsigned long long sZ2[32][8];    // {z,z} packed, 2 KB

    int tid = threadIdx.x;

    // ---- preamble: weights only (kernel inputs), safe before PDL wait ----
    for (int idx = tid; idx < CF * 8; idx += 256) {
        int k = idx / CF;
        int c = idx - k * CF;
        sW[c * 8 + k] = Wfc[idx];
    }
    __syncthreads();

    int c0 = tid * 4;
    bool active = (c0 < CF);
    unsigned long long wp01[8], wp23[8], bias01 = 0, bias23 = 0;
    if (active) {
#pragma unroll
        for (int k = 0; k < 8; k++) {
            wp01[k] = pack2(sW[(c0 + 0) * 8 + k], sW[(c0 + 1) * 8 + k]);
            wp23[k] = pack2(sW[(c0 + 2) * 8 + k], sW[(c0 + 3) * 8 + k]);
        }
        bias01 = pack2(__ldg(&bfc[c0 + 0]), __ldg(&bfc[c0 + 1]));
        bias23 = pack2(__ldg(&bfc[c0 + 2]), __ldg(&bfc[c0 + 3]));
    }

    PDL_WAIT();   // g_z2 (g2 output) valid after this

    for (int tile = blockIdx.x; tile < NTILES; tile += gridDim.x) {
        int node0 = tile * 32;
        __syncthreads();
        sZ2[tid >> 3][tid & 7] = g_z2[node0 * 8 + tid];
        __syncthreads();

        if (active) {
#pragma unroll 1
            for (int g = 0; g < 8; g++) {
#pragma unroll
                for (int n = 0; n < 4; n++) {
                    int nn = g * 4 + n;
                    unsigned long long acc01 = bias01, acc23 = bias23;
#pragma unroll
                    for (int k = 0; k < 8; k++) {
                        unsigned long long zb = sZ2[nn][k];
                        acc01 = fma2(zb, wp01[k], acc01);
                        acc23 = fma2(zb, wp23[k], acc23);
                    }
                    float2 r01 = unpack2(acc01);
                    float2 r23 = unpack2(acc23);
                    float4 r = make_float4(r01.x, r01.y, r23.x, r23.y);
                    int node = node0 + nn;
                    __stcs(reinterpret_cast<float4*>(&out[node * CF + c0]), r);
                }
            }
        }
    }

    // ---- epilogue: reset g_cnt for the next call (replaces k_zero) ----
    int gt = blockIdx.x * blockDim.x + tid;          // 189,440 threads
    for (int i = gt; i < Nn; i += FCBLOCKS * 256) g_cnt[i] = 0;
}

static inline void launch_pdl(void* func, dim3 grid, dim3 block,
                              void** args) {
    cudaLaunchConfig_t cfg = {};
    cfg.gridDim = grid;
    cfg.blockDim = block;
    cfg.dynamicSmemBytes = 0;
    cfg.stream = 0;
    cudaLaunchAttribute attr[1];
    attr[0].id = cudaLaunchAttributeProgrammaticStreamSerialization;
    attr[0].val.programmaticStreamSerializationAllowed = 1;
    cfg.attrs = attr;
    cfg.numAttrs = 1;
    cudaLaunchKernelExC(&cfg, func, args);
}

extern "C" void kernel_launch(void* const* d_in, const int* in_sizes, int n_in,
                              void* d_out, int out_size) {
    const float* x   = (const float*)d_in[0];
    const int*   ei  = (const int*)d_in[1];
    const float* W1  = (const float*)d_in[2];
    const float* b1  = (const float*)d_in[3];
    const float* W2  = (const float*)d_in[4];
    const float* b2  = (const float*)d_in[5];
    const float* Wfc = (const float*)d_in[6];
    const float* bfc = (const float*)d_in[7];
    float* out = (float*)d_out;

    const int TB = 256;
    // k_build launched plainly (no PDL): must strictly follow the previous
    // call's k_out (which re-zeros g_cnt).
    k_build<<<(Ee / 4 + TB - 1) / TB, TB>>>(ei);

    {   // k_prep with PDL on k_build
        void* args[] = {(void*)&x};
        launch_pdl((void*)k_prep, dim3((Nn + TB - 1) / TB), dim3(TB), args);
    }
    {   // k_l1 with PDL on k_prep
        void* args[] = {(void*)&W1, (void*)&b1, (void*)&W2};
        launch_pdl((void*)k_l1, dim3((Nn * 8 + TB - 1) / TB), dim3(TB), args);
    }
    {   // k_g2 with PDL on k_l1
        void* args[] = {(void*)&b2};
        launch_pdl((void*)k_g2, dim3((Nn * 8 + TB - 1) / TB), dim3(TB), args);
    }
    {   // k_out with PDL on k_g2
        void* args[] = {(void*)&Wfc, (void*)&bfc, (void*)&out};
        launch_pdl((void*)k_out, dim3(FCBLOCKS), dim3(TB), args);
    }
}